// round 17
// baseline (speedup 1.0000x reference)
#include <cuda_runtime.h>
#include <cuda_bf16.h>
#include <cstdint>

#define N_NODES 50000
#define N_EDGES 800000
#define DIM 128
#define NL 3
#define PAD 64      // max degree slack: P(Poisson(16) >= 64) ~ 1e-19 per node
#define STR 136     // padded bf16 row stride (136*2=272B -> conflict-free frags)
#define NROWPAD 50048

typedef unsigned long long u64;
typedef unsigned int u32;
typedef unsigned short us;

// Scratch (allocation-free rule: __device__ globals)
__device__ float g_z[(size_t)N_NODES * DIM];        // inter-layer fp32 activations
__device__ int   g_cnt[N_NODES];                    // per-dst degree counter
__device__ int   g_srcs[(size_t)N_NODES * PAD];     // padded CSR adjacency
__device__ int   g_is64;
// Split-bf16 activation images in padded [row][STR] layout (producer-written)
__device__ us g_hA_hi[(size_t)NROWPAD * STR];
__device__ us g_hA_lo[(size_t)NROWPAD * STR];
__device__ us g_tA_hi[(size_t)NROWPAD * STR];
__device__ us g_tA_lo[(size_t)NROWPAD * STR];
// Padded [n][k] bf16 images of W^T (hi/lo split), 6 matrices (3 layers x 2)
__device__ us g_Wimg_hi[6 * DIM * STR];
__device__ us g_Wimg_lo[6 * DIM * STR];

__device__ __forceinline__ void bsplit(float v, us& h, us& l) {
    __nv_bfloat16 bh = __float2bfloat16(v);
    float r = v - __bfloat162float(bh);
    __nv_bfloat16 bl = __float2bfloat16(r);
    h = __bfloat16_as_ushort(bh);
    l = __bfloat16_as_ushort(bl);
}

// mma.sync m16n8k16 row.col f32.bf16.bf16.f32 (sm_80+ PTX, tensor pipe)
__device__ __forceinline__ void mma16816(float c[4], const u32 a[4], u32 b0, u32 b1) {
    asm volatile(
        "mma.sync.aligned.m16n8k16.row.col.f32.bf16.bf16.f32 "
        "{%0,%1,%2,%3}, {%4,%5,%6,%7}, {%8,%9}, {%0,%1,%2,%3};"
        : "+f"(c[0]), "+f"(c[1]), "+f"(c[2]), "+f"(c[3])
        : "r"(a[0]), "r"(a[1]), "r"(a[2]), "r"(a[3]), "r"(b0), "r"(b1));
}

// ---------------------------------------------------------------------------
// Graph preprocessing
// ---------------------------------------------------------------------------
__global__ void detect_idx_kernel(const int* __restrict__ ei_i32) {
    const int lane = threadIdx.x;  // 32
    int bad = (ei_i32[2 * lane + 1] != 0) | (ei_i32[2 * (lane + 32) + 1] != 0);
    unsigned m = __ballot_sync(0xffffffffu, bad);
    if (lane == 0) g_is64 = (m == 0);
}

__global__ void zero_cnt_kernel() {
    int i = blockIdx.x * blockDim.x + threadIdx.x;
    if (i < N_NODES) g_cnt[i] = 0;
}

__global__ void fill_kernel(const void* __restrict__ ei) {
    int e = blockIdx.x * blockDim.x + threadIdx.x;
    if (e >= N_EDGES) return;
    int s, d;
    if (g_is64) {
        const long long* p = (const long long*)ei;
        s = (int)p[e];
        d = (int)p[N_EDGES + e];
    } else {
        const int* p = (const int*)ei;
        s = p[e];
        d = p[N_EDGES + e];
    }
    int slot = atomicAdd(&g_cnt[d], 1);
    if (slot < PAD) g_srcs[(size_t)d * PAD + slot] = s;
}

// Build padded bf16 hi/lo images of W^T: img[n][k] = W[k][n]. 384 blocks.
__global__ void convert_w_kernel(const float* __restrict__ Ws1,
                                 const float* __restrict__ Ws2) {
    const int mat = blockIdx.x >> 6;          // 0..5
    const int chunk = blockIdx.x & 63;        // 0..63
    const float* W = ((mat & 1) ? Ws2 : Ws1) + (size_t)(mat >> 1) * DIM * DIM;
    us* hi = g_Wimg_hi + (size_t)mat * DIM * STR;
    us* lo = g_Wimg_lo + (size_t)mat * DIM * STR;
    const int idx = chunk * 256 + threadIdx.x;   // 0..16383
    const int n = idx >> 7, k = idx & 127;
    us h, l;
    bsplit(W[k * DIM + n], h, l);
    hi[n * STR + k] = h;
    lo[n * STR + k] = l;
}

// ---------------------------------------------------------------------------
// Aggregation: warp per node, h[n] = z[n] + sum_{s in adj(n)} z[s].
// Adjacency loaded COALESCED into lanes (one LDG.32/warp), broadcast by
// shuffle; gathers issued in 8-wide predicated batches (MLP=8) with two
// accumulators. Typical node (deg~16): 2 overlapped L2 round-trips instead
// of ~8 serialized ones. Output written as split-bf16 padded images.
// ---------------------------------------------------------------------------
__global__ void aggregate_kernel(const float* __restrict__ z,
                                 us* __restrict__ out_hi,
                                 us* __restrict__ out_lo) {
    const int w = (blockIdx.x * blockDim.x + threadIdx.x) >> 5;
    if (w >= N_NODES) return;
    const int lane = threadIdx.x & 31;
    const float* zp = z + lane * 4;

    const int* adj = g_srcs + (size_t)w * PAD;
    int deg = g_cnt[w];
    if (deg > PAD) deg = PAD;

    // Coalesced adjacency fetch: lane j holds adj[j] for j < min(deg,32).
    int myadj = 0;
    if (lane < deg) myadj = adj[lane];

    float4 acc = *(const float4*)(zp + (size_t)w * DIM);  // self term
    float4 acc2 = make_float4(0.f, 0.f, 0.f, 0.f);

    const int nb = deg < 32 ? deg : 32;
#pragma unroll
    for (int base = 0; base < 32; base += 8) {
        if (base < nb) {
            const int cnt = nb - base;
            float4 v[8];
#pragma unroll
            for (int j = 0; j < 8; j++) {
                const int s = __shfl_sync(0xffffffffu, myadj, base + j);
                if (j < cnt) v[j] = *(const float4*)(zp + (size_t)s * DIM);
                else         v[j] = make_float4(0.f, 0.f, 0.f, 0.f);
            }
            acc.x  += (v[0].x + v[1].x) + (v[2].x + v[3].x);
            acc2.x += (v[4].x + v[5].x) + (v[6].x + v[7].x);
            acc.y  += (v[0].y + v[1].y) + (v[2].y + v[3].y);
            acc2.y += (v[4].y + v[5].y) + (v[6].y + v[7].y);
            acc.z  += (v[0].z + v[1].z) + (v[2].z + v[3].z);
            acc2.z += (v[4].z + v[5].z) + (v[6].z + v[7].z);
            acc.w  += (v[0].w + v[1].w) + (v[2].w + v[3].w);
            acc2.w += (v[4].w + v[5].w) + (v[6].w + v[7].w);
        }
    }
    // Rare tail (deg > 32): scalar loop over adjacency array.
    for (int e = 32; e < deg; e++) {
        const float4 v = *(const float4*)(zp + (size_t)adj[e] * DIM);
        acc.x += v.x; acc.y += v.y; acc.z += v.z; acc.w += v.w;
    }
    acc.x += acc2.x; acc.y += acc2.y; acc.z += acc2.z; acc.w += acc2.w;

    us h0, h1, h2, h3, l0, l1, l2, l3;
    bsplit(acc.x, h0, l0); bsplit(acc.y, h1, l1);
    bsplit(acc.z, h2, l2); bsplit(acc.w, h3, l3);
    const size_t off = (size_t)w * STR + lane * 4;
    *(uint2*)(out_hi + off) = make_uint2((u32)h0 | ((u32)h1 << 16),
                                         (u32)h2 | ((u32)h3 << 16));
    *(uint2*)(out_lo + off) = make_uint2((u32)l0 | ((u32)l1 << 16),
                                         (u32)l2 | ((u32)l3 << 16));
}

// ---------------------------------------------------------------------------
// Tensor-pipe GEMM via mma.sync (bf16x3 split precision):
// C = relu(A @ W + bias), 64-row tile x full 128 cols, K=128.
// smem = 102KB -> 2 CTAs/SM (16 warps) so staging overlaps compute.
// 8 warps: 2m x 4n, warp tile 32x32 (2x4 m16n8k16).
// MODE 0: fp32 C (guarded).  MODE 1: split-bf16 C (padded images).
// ---------------------------------------------------------------------------
#define SMEM_GEMM (2 * 64 * STR * 2 + 2 * 128 * STR * 2)   // 104448 B

template <int MODE>
__global__ __launch_bounds__(256, 2)
void gemm_mma(const us* __restrict__ Ahi, const us* __restrict__ Alo, int mat,
              const float* __restrict__ bias,
              float* __restrict__ Cf,
              us* __restrict__ Chi, us* __restrict__ Clo) {
    extern __shared__ char smem[];
    us* sAh = (us*)smem;                 // [64][STR]
    us* sAl = sAh + 64 * STR;
    us* sWh = sAl + 64 * STR;            // [128][STR]
    us* sWl = sWh + 128 * STR;

    const int tid = threadIdx.x;   // 256
    const int wid = tid >> 5, lane = tid & 31;
    const int m0 = blockIdx.x * 64;

    // Pure memcpy staging (uint4, coalesced): W 2x2176, A 2x1088.
    {
        const uint4* wh = (const uint4*)(g_Wimg_hi + (size_t)mat * DIM * STR);
        const uint4* wl = (const uint4*)(g_Wimg_lo + (size_t)mat * DIM * STR);
        const uint4* ah = (const uint4*)(Ahi + (size_t)m0 * STR);
        const uint4* al = (const uint4*)(Alo + (size_t)m0 * STR);
        uint4* dwh = (uint4*)sWh;
        uint4* dwl = (uint4*)sWl;
        uint4* dah = (uint4*)sAh;
        uint4* dal = (uint4*)sAl;
#pragma unroll
        for (int it = 0; it < 9; it++) {          // 2176 = 8.5 * 256
            const int i = tid + it * 256;
            if (i < 128 * STR / 8) { dwh[i] = wh[i]; dwl[i] = wl[i]; }
        }
#pragma unroll
        for (int it = 0; it < 5; it++) {          // 1088 = 4.25 * 256
            const int i = tid + it * 256;
            if (i < 64 * STR / 8) { dah[i] = ah[i]; dal[i] = al[i]; }
        }
    }
    __syncthreads();

    const int wm = wid & 1;    // 32-row group (0..1)
    const int wn = wid >> 1;   // 32-col group (0..3)
    const int g = lane >> 2, t = lane & 3;

    float acc[2][4][4];
#pragma unroll
    for (int mt = 0; mt < 2; mt++)
#pragma unroll
        for (int nt = 0; nt < 4; nt++)
#pragma unroll
            for (int r = 0; r < 4; r++) acc[mt][nt][r] = 0.f;

#pragma unroll
    for (int ks = 0; ks < 8; ks++) {
        const int k0 = ks * 16;
        u32 ah[2][4], al[2][4];
#pragma unroll
        for (int mt = 0; mt < 2; mt++) {
            const int base = (wm * 32 + mt * 16 + g) * STR + k0 + t * 2;
            ah[mt][0] = *(const u32*)(sAh + base);
            ah[mt][1] = *(const u32*)(sAh + base + 8 * STR);
            ah[mt][2] = *(const u32*)(sAh + base + 8);
            ah[mt][3] = *(const u32*)(sAh + base + 8 * STR + 8);
            al[mt][0] = *(const u32*)(sAl + base);
            al[mt][1] = *(const u32*)(sAl + base + 8 * STR);
            al[mt][2] = *(const u32*)(sAl + base + 8);
            al[mt][3] = *(const u32*)(sAl + base + 8 * STR + 8);
        }
#pragma unroll
        for (int nt = 0; nt < 4; nt++) {
            const int bbase = (wn * 32 + nt * 8 + g) * STR + k0 + t * 2;
            const u32 bh0 = *(const u32*)(sWh + bbase);
            const u32 bh1 = *(const u32*)(sWh + bbase + 8);
            const u32 bl0 = *(const u32*)(sWl + bbase);
            const u32 bl1 = *(const u32*)(sWl + bbase + 8);
#pragma unroll
            for (int mt = 0; mt < 2; mt++) {
                mma16816(acc[mt][nt], ah[mt], bh0, bh1);
                mma16816(acc[mt][nt], ah[mt], bl0, bl1);
                mma16816(acc[mt][nt], al[mt], bh0, bh1);
            }
        }
    }

    // Epilogue: bias + relu.
#pragma unroll
    for (int nt = 0; nt < 4; nt++) {
        const int col = wn * 32 + nt * 8 + t * 2;
        const float b0 = bias[col], b1 = bias[col + 1];
#pragma unroll
        for (int mt = 0; mt < 2; mt++) {
            const int row0 = m0 + wm * 32 + mt * 16 + g;
            const int row1 = row0 + 8;
            const float v00 = fmaxf(acc[mt][nt][0] + b0, 0.f);
            const float v01 = fmaxf(acc[mt][nt][1] + b1, 0.f);
            const float v10 = fmaxf(acc[mt][nt][2] + b0, 0.f);
            const float v11 = fmaxf(acc[mt][nt][3] + b1, 0.f);
            if (MODE == 0) {
                if (row0 < N_NODES) {
                    float2 o; o.x = v00; o.y = v01;
                    *(float2*)(Cf + (size_t)row0 * DIM + col) = o;
                }
                if (row1 < N_NODES) {
                    float2 o; o.x = v10; o.y = v11;
                    *(float2*)(Cf + (size_t)row1 * DIM + col) = o;
                }
            } else {
                us h0, l0, h1, l1, h2, l2, h3, l3;
                bsplit(v00, h0, l0); bsplit(v01, h1, l1);
                bsplit(v10, h2, l2); bsplit(v11, h3, l3);
                *(u32*)(Chi + (size_t)row0 * STR + col) = (u32)h0 | ((u32)h1 << 16);
                *(u32*)(Clo + (size_t)row0 * STR + col) = (u32)l0 | ((u32)l1 << 16);
                *(u32*)(Chi + (size_t)row1 * STR + col) = (u32)h2 | ((u32)h3 << 16);
                *(u32*)(Clo + (size_t)row1 * STR + col) = (u32)l2 | ((u32)l3 << 16);
            }
        }
    }
}

extern "C" void kernel_launch(void* const* d_in, const int* in_sizes, int n_in,
                              void* d_out, int out_size) {
    const float* x   = (const float*)d_in[0];
    const float* Ws1 = (const float*)d_in[1];
    const float* bs1 = (const float*)d_in[2];
    const float* Ws2 = (const float*)d_in[3];
    const float* bs2 = (const float*)d_in[4];
    const void*  ei  = d_in[5];
    float* out = (float*)d_out;

    cudaFuncSetAttribute(gemm_mma<0>, cudaFuncAttributeMaxDynamicSharedMemorySize,
                         SMEM_GEMM);
    cudaFuncSetAttribute(gemm_mma<1>, cudaFuncAttributeMaxDynamicSharedMemorySize,
                         SMEM_GEMM);

    float* z_buf;
    us *hA_hi, *hA_lo, *tA_hi, *tA_lo;
    cudaGetSymbolAddress((void**)&z_buf, g_z);
    cudaGetSymbolAddress((void**)&hA_hi, g_hA_hi);
    cudaGetSymbolAddress((void**)&hA_lo, g_hA_lo);
    cudaGetSymbolAddress((void**)&tA_hi, g_tA_hi);
    cudaGetSymbolAddress((void**)&tA_lo, g_tA_lo);

    const int edge_blocks = (N_EDGES + 255) / 256;          // 3125
    const int gemm_blocks = (N_NODES + 63) / 64;            // 782
    const int agg_blocks  = (N_NODES * 32 + 255) / 256;     // 6250

    // One-time preprocessing (edge_index and W reused by all layers)
    detect_idx_kernel<<<1, 32>>>((const int*)ei);
    zero_cnt_kernel<<<(N_NODES + 255) / 256, 256>>>();
    fill_kernel<<<edge_blocks, 256>>>(ei);
    convert_w_kernel<<<384, 256>>>(Ws1, Ws2);

    const float* zcur = x;
    for (int l = 0; l < NL; l++) {
        aggregate_kernel<<<agg_blocks, 256>>>(zcur, hA_hi, hA_lo);
        // GEMM1: t = relu(h@W1+b1), written as split-bf16 images
        gemm_mma<1><<<gemm_blocks, 256, SMEM_GEMM>>>(
            hA_hi, hA_lo, 2 * l + 0, bs1 + (size_t)l * DIM,
            nullptr, tA_hi, tA_lo);
        // GEMM2: z = relu(t@W2+b2), fp32 (next aggregate / final out)
        float* zout = (l == NL - 1) ? out : z_buf;
        gemm_mma<0><<<gemm_blocks, 256, SMEM_GEMM>>>(
            tA_hi, tA_lo, 2 * l + 1, bs2 + (size_t)l * DIM,
            zout, nullptr, nullptr);
        zcur = zout;
    }
}